// round 14
// baseline (speedup 1.0000x reference)
#include <cuda_runtime.h>
#include <math.h>

#define P        256
#define NT       480
#define NBLK     1000
#define NWIN     976
#define TRI      32896        // P*(P+1)/2
#define SIG_CHUNK  61
#define SIG_NCHUNK 16
#define LPS      260          // panel row stride (floats), %4==0
#define CT       128
#define SOLVE_SMEM ((16*LPS + 3*256 + 64) * 4)
#define FULLM 0xffffffffu

__device__ float g_wc[64];
__device__ float g_H[(size_t)NBLK * TRI];
__device__ float g_Sigma[(size_t)NWIN * TRI];
__device__ float g_V[NBLK * P];
__device__ float g_mean[NWIN * P];
__device__ float g_res[2 * NWIN];

__device__ __forceinline__ int offj(int j) { return j * P - ((j * (j - 1)) >> 1); }

// ---------------- K0: weights & constants ---------------------------------
__global__ void k_setup(const float* __restrict__ a_in) {
    double a = (double)a_in[0];
    double s1 = 0.0, ap = 1.0;
    for (int u = 0; u < NT; u++) { s1 += ap; ap *= a; }
    double c = (double)NT / s1;
    double s2 = 0.0, a2 = a * a; ap = 1.0;
    for (int u = 0; u < NT; u++) { s2 += ap; ap *= a2; }
    s2 *= c * c;
    double denom = (double)NT - s2 / (double)NT;
    for (int k = 0; k < 24; k++) g_wc[k]      = (float)pow(a, 20.0 * (23 - k));
    for (int u = 0; u < 20; u++) g_wc[24 + u] = (float)pow(a, (double)(19 - u));
    g_wc[44] = (float)c;
    g_wc[45] = (float)(1.0 / denom);
    g_wc[46] = (float)pow(a, 20.0);
    g_wc[47] = (float)pow(a, 460.0);
    g_wc[48] = (float)(c / (double)NT);
}

// ---------------- K1: block Grams (packed lower) ---------------------------
__global__ void __launch_bounds__(256) k_gram(const float* __restrict__ Y) {
    const int lt = blockIdx.x % 10;
    const int b  = blockIdx.x / 10;
    int ti = 0;
    while (((ti + 1) * (ti + 2)) / 2 <= lt) ti++;
    const int tj = lt - (ti * (ti + 1)) / 2;

    __shared__ __align__(16) float As[20][64];
    __shared__ __align__(16) float Bs[20][64];
    __shared__ float Cs[64][65];
    const int tid = threadIdx.x;
    for (int idx = tid; idx < 20 * 64; idx += 256) {
        int u = idx >> 6, cc = idx & 63;
        size_t row = (size_t)(b * 20 + u) * P;
        As[u][cc] = g_wc[24 + u] * Y[row + ti * 64 + cc];
        Bs[u][cc] = Y[row + tj * 64 + cc];
    }
    __syncthreads();

    const int tx = tid & 15, ty = tid >> 4;
    float acc[4][4];
#pragma unroll
    for (int r = 0; r < 4; r++)
#pragma unroll
        for (int c = 0; c < 4; c++) acc[r][c] = 0.f;

#pragma unroll
    for (int u = 0; u < 20; u++) {
        float4 av = *(const float4*)&As[u][ty * 4];
        float4 bv = *(const float4*)&Bs[u][tx * 4];
        float ar[4] = {av.x, av.y, av.z, av.w};
        float br[4] = {bv.x, bv.y, bv.z, bv.w};
#pragma unroll
        for (int r = 0; r < 4; r++)
#pragma unroll
            for (int c = 0; c < 4; c++) acc[r][c] += ar[r] * br[c];
    }
#pragma unroll
    for (int r = 0; r < 4; r++)
#pragma unroll
        for (int c = 0; c < 4; c++) Cs[ty * 4 + r][tx * 4 + c] = acc[r][c];
    __syncthreads();

    float* Hb = g_H + (size_t)b * TRI;
    for (int idx = tid; idx < 64 * 64; idx += 256) {
        int cc = idx >> 6, rr = idx & 63;
        if (ti == tj && rr < cc) continue;
        int j = tj * 64 + cc, i = ti * 64 + rr;
        Hb[offj(j) + i - j] = Cs[rr][cc];
    }
}

// ---------------- K2: weighted block row-sums ------------------------------
__global__ void k_vsum(const float* __restrict__ Y) {
    const int b = blockIdx.x, i = threadIdx.x;
    float s = 0.f;
#pragma unroll
    for (int u = 0; u < 20; u++)
        s += g_wc[24 + u] * Y[(size_t)(b * 20 + u) * P + i];
    g_V[b * P + i] = s;
}

// ---------------- K3: per-window means --------------------------------------
__global__ void k_mean() {
    const int w = blockIdx.x, i = threadIdx.x;
    float s = 0.f;
#pragma unroll
    for (int k = 0; k < 24; k++)
        s += g_wc[k] * g_V[(w + k) * P + i];
    g_mean[w * P + i] = s * g_wc[48];
}

// ---------------- K4: Sigma via sliding recurrence --------------------------
__global__ void k_sigma() {
    int e = blockIdx.x * 256 + threadIdx.x;
    if (e >= TRI) return;
    int c = blockIdx.y;
    int j = (int)((513.0 - sqrt(513.0 * 513.0 - 8.0 * (double)e)) * 0.5);
    if (j < 0) j = 0; if (j > 255) j = 255;
    while (j < 255 && offj(j + 1) <= e) j++;
    while (j > 0 && offj(j) > e) j--;
    int i = e - offj(j) + j;

    const float a20 = g_wc[46], gg0 = g_wc[47], cw = g_wc[44], inv = g_wc[45];
    const int w0 = c * SIG_CHUNK;
    float T = 0.f;
    for (int k = 0; k < 24; k++) T += g_wc[k] * g_H[(size_t)(w0 + k) * TRI + e];
    for (int s = 0; s < SIG_CHUNK; s++) {
        int w = w0 + s;
        float m = g_mean[w * P + i] * g_mean[w * P + j];
        g_Sigma[(size_t)w * TRI + e] = (cw * T - 480.0f * m) * inv;
        if (s + 1 < SIG_CHUNK)
            T = a20 * (T - gg0 * g_H[(size_t)w * TRI + e]) + g_H[(size_t)(w + 24) * TRI + e];
    }
}

// ---------------- K5: out-of-core Cholesky, 8 CTAs/SM -----------------------
__global__ void __launch_bounds__(CT, 8) k_chol(const float* __restrict__ Y) {
    extern __shared__ float sm[];
    float* Lp  = sm;                      // 16 x LPS panel (abs row idx)
    float* yv  = Lp + 16 * LPS;           // 256
    float* zv  = yv + 256;                // 256
    float* rd  = zv + 256;                // 256: 1/L[j][j]
    float* red = rd + 256;                // 64 scratch
    const int w = blockIdx.x;
    const int tid = threadIdx.x;
    const int lane = tid & 31;
    const int wid  = tid >> 5;            // 0..3
    float* A = g_Sigma + (size_t)w * TRI; // global, in-place factor

    // ---- factorization: 16 panels of 16 ----
    for (int kb = 0; kb < 16; kb++) {
        const int j0  = 16 * kb;
        const int s0n = j0 + 16;
        const int hp  = P - s0n;

        // stage panel cols j0..j0+15 global -> smem (coalesced)
#pragma unroll 1
        for (int k = 0; k < 16; k++) {
            const float* colg = A + offj(j0 + k) - (j0 + k);
            for (int i = j0 + k + tid; i < P; i += CT)
                Lp[k * LPS + i] = colg[i];
        }
        __syncthreads();

        // warp0: register Cholesky of 16x16 diag block (in panel)
        if (wid == 0) {
            const int r = lane;
            float a[16];
#pragma unroll
            for (int c = 0; c < 16; c++)
                a[c] = (r < 16 && r >= c) ? Lp[c * LPS + j0 + r] : 0.f;
#pragma unroll
            for (int jj = 0; jj < 16; jj++) {
                float d = __shfl_sync(FULLM, a[jj], jj);
                float rinv = rsqrtf(d);
                if (r == jj) rd[j0 + jj] = rinv;
                a[jj] *= rinv;
#pragma unroll
                for (int c = jj + 1; c < 16; c++) {
                    float Lcjj = __shfl_sync(FULLM, a[jj], c);
                    if (r >= c) a[c] -= a[jj] * Lcjj;
                }
            }
#pragma unroll
            for (int c = 0; c < 16; c++)
                if (r < 16 && r >= c) Lp[c * LPS + j0 + r] = a[c];
        }
        __syncthreads();

        // row-parallel TRSM (strided; hp up to 240, CT=128 -> <=2 passes)
        for (int i = s0n + tid; i < P; i += CT) {
            float y[16];
#pragma unroll
            for (int k = 0; k < 16; k++) y[k] = Lp[k * LPS + i];
#pragma unroll
            for (int k = 0; k < 16; k++) {
                y[k] *= rd[j0 + k];
                const float yk = y[k];
#pragma unroll
                for (int m = 1; m < 16; m++)
                    if (k + m < 16) y[k + m] -= Lp[k * LPS + j0 + k + m] * yk;
            }
#pragma unroll
            for (int k = 0; k < 16; k++) Lp[k * LPS + i] = y[k];
        }
        __syncthreads();

        // write back factored panel to global (coalesced)
#pragma unroll 1
        for (int k = 0; k < 16; k++) {
            float* colg = A + offj(j0 + k) - (j0 + k);
            for (int i = j0 + k + tid; i < P; i += CT)
                colg[i] = Lp[k * LPS + i];
        }

        // trailing SYRK: 64-row x 8-col tiles (two 32-row groups per lane)
        if (hp > 0) {
            const int mtr = (hp + 63) >> 6;
            const int ncj = hp >> 3;
            const int nrect = mtr * ncj;
            for (int t = wid; t < nrect; t += 4) {
                const int bi = t / ncj;
                const int cj = t - bi * ncj;
                if (cj > 8 * bi + 7) continue;     // above diagonal band
                const int i1  = s0n + 64 * bi + lane;
                const int i2  = i1 + 32;
                const int jc0 = s0n + 8 * cj;
                float acc1[8], acc2[8];
#pragma unroll
                for (int c = 0; c < 8; c++) { acc1[c] = 0.f; acc2[c] = 0.f; }
#pragma unroll
                for (int k = 0; k < 16; k++) {
                    const float* lk = Lp + k * LPS;
                    const float av1 = (i1 < P) ? lk[i1] : 0.f;  // coalesced LDS
                    const float av2 = (i2 < P) ? lk[i2] : 0.f;
                    float4 b0 = *(const float4*)&lk[jc0];       // broadcast
                    float4 b1 = *(const float4*)&lk[jc0 + 4];
                    float br[8] = {b0.x, b0.y, b0.z, b0.w, b1.x, b1.y, b1.z, b1.w};
#pragma unroll
                    for (int c = 0; c < 8; c++) {
                        acc1[c] = fmaf(av1, br[c], acc1[c]);
                        acc2[c] = fmaf(av2, br[c], acc2[c]);
                    }
                }
                if (i1 < P) {
                    float g[8];
#pragma unroll
                    for (int c = 0; c < 8; c++) {
                        const int j = jc0 + c;
                        g[c] = (i1 >= j) ? A[offj(j) + i1 - j] : 0.f;
                    }
#pragma unroll
                    for (int c = 0; c < 8; c++) {
                        const int j = jc0 + c;
                        if (i1 >= j) A[offj(j) + i1 - j] = g[c] - acc1[c];
                    }
                }
                if (i2 < P) {
                    float g[8];
#pragma unroll
                    for (int c = 0; c < 8; c++) {
                        const int j = jc0 + c;
                        g[c] = (i2 >= j) ? A[offj(j) + i2 - j] : 0.f;
                    }
#pragma unroll
                    for (int c = 0; c < 8; c++) {
                        const int j = jc0 + c;
                        if (i2 >= j) A[offj(j) + i2 - j] = g[c] - acc2[c];
                    }
                }
            }
        }
        __syncthreads();
    }

    // ---- forward: L y = 1 (L in global) ----
    for (int r = tid; r < P; r += CT) yv[r] = 1.0f;
    __syncthreads();
    for (int jb = 0; jb < 16; jb++) {
        const int j0 = jb * 16;
        if (wid == 0) {
            const int r = lane;
            float a[16];
#pragma unroll
            for (int c = 0; c < 16; c++)
                a[c] = (r < 16 && r >= c) ? A[offj(j0 + c) + r - c] : 0.f;
            float y   = (r < 16) ? yv[j0 + r] : 0.f;
            float rmy = (r < 16) ? rd[j0 + r] : 0.f;
#pragma unroll
            for (int jj = 0; jj < 16; jj++) {
                if (r == jj) y *= rmy;
                float yjj = __shfl_sync(FULLM, y, jj);
                if (r > jj && r < 16) y -= a[jj] * yjj;
            }
            if (r < 16) yv[j0 + r] = y;
        }
        __syncthreads();
        for (int r = j0 + 16 + tid; r < P; r += CT) {
            float s = 0.f;
#pragma unroll
            for (int jj = 0; jj < 16; jj++)
                s += A[offj(j0 + jj) + r - (j0 + jj)] * yv[j0 + jj];
            yv[r] -= s;
        }
        __syncthreads();
    }

    // ---- backward: L^T z = y (gather form, coalesced column dots) ----
    for (int r = tid; r < P; r += CT) zv[r] = yv[r];
    __syncthreads();
    for (int jb = 15; jb >= 0; jb--) {
        const int j0 = jb * 16;
        const int base = j0 + 16, len = P - base;
        if (len > 0) {
#pragma unroll
            for (int h = 0; h < 4; h++) {
                const int j = j0 + wid + 4 * h;
                const float* colj = A + offj(j) + (base - j);
                float s = 0.f;
                for (int r = lane; r < len; r += 32) s += colj[r] * zv[base + r];
#pragma unroll
                for (int o = 16; o > 0; o >>= 1) s += __shfl_down_sync(FULLM, s, o);
                if (lane == 0) red[wid + 4 * h] = s;
            }
        }
        __syncthreads();
        if (wid == 0) {
            const int c = lane;
            float a[16];
#pragma unroll
            for (int rr = 0; rr < 16; rr++)
                a[rr] = (c < 16 && rr >= c) ? A[offj(j0 + c) + rr - c] : 0.f;
            float corr = (c < 16 && len > 0) ? red[c] : 0.f;
            float z   = (c < 16) ? zv[j0 + c] - corr : 0.f;
            float rmz = (c < 16) ? rd[j0 + c] : 0.f;
#pragma unroll
            for (int jj = 15; jj >= 0; jj--) {
                if (c == jj) z *= rmz;
                float zjj = __shfl_sync(FULLM, z, jj);
                if (c < jj) z -= a[jj] * zjj;
            }
            if (c < 16) zv[j0 + c] = z;
        }
        __syncthreads();
    }

    // ---- normalize scale = 256 / sum(z) ----
    float s = zv[tid] + zv[tid + CT];
#pragma unroll
    for (int o = 16; o > 0; o >>= 1) s += __shfl_down_sync(FULLM, s, o);
    if (lane == 0) red[wid] = s;
    __syncthreads();
    if (tid == 0) {
        float tot = red[0] + red[1] + red[2] + red[3];
        red[40] = 256.0f / tot;
    }
    __syncthreads();
    const float scale = red[40];

    // ---- epilogue: 4 warps x 5 test days ----
#pragma unroll
    for (int kq = 0; kq < 5; kq++) {
        const int t = 4 * kq + wid;
        const float* yr = Y + (size_t)((w + 24) * 20 + t) * P;
        float part = 0.f;
#pragma unroll
        for (int q = 0; q < 8; q++)
            part += yr[lane + 32 * q] * zv[lane + 32 * q];
#pragma unroll
        for (int o = 16; o > 0; o >>= 1) part += __shfl_down_sync(FULLM, part, o);
        if (lane == 0) red[t] = part * scale;
    }
    __syncthreads();
    if (tid == 0) {
        float se = 0.f, sq = 0.f;
#pragma unroll
        for (int t = 0; t < 20; t++) { float rt = red[t]; se += rt; sq += rt * rt; }
        g_res[w] = se;
        g_res[NWIN + w] = (sq - se * se / 20.f) / 19.f;
    }
}

// ---------------- K6: final reduction ---------------------------------------
__global__ void k_final(float* out) {
    __shared__ float rb[64];
    const int tid = threadIdx.x;
    float se = 0.f, ss = 0.f;
    for (int w = tid; w < NWIN; w += 256) { se += g_res[w]; ss += g_res[NWIN + w]; }
#pragma unroll
    for (int o = 16; o > 0; o >>= 1) {
        se += __shfl_down_sync(FULLM, se, o);
        ss += __shfl_down_sync(FULLM, ss, o);
    }
    if ((tid & 31) == 0) { rb[tid >> 5] = se; rb[32 + (tid >> 5)] = ss; }
    __syncthreads();
    if (tid == 0) {
        float te = 0.f, ts = 0.f;
        for (int k = 0; k < 8; k++) { te += rb[k]; ts += rb[32 + k]; }
        float mu  = te / (float)NWIN / 20.f * 252.f;
        float vol = sqrtf(ts / (float)NWIN * 252.f);
        out[0] = vol;
        out[1] = mu;
        out[2] = mu / vol;
    }
}

extern "C" void kernel_launch(void* const* d_in, const int* in_sizes, int n_in,
                              void* d_out, int out_size) {
    const float* Y = (const float*)d_in[0];
    const float* a = (const float*)d_in[1];
    k_setup<<<1, 1>>>(a);
    k_gram<<<NBLK * 10, 256>>>(Y);
    k_vsum<<<NBLK, 256>>>(Y);
    // Diagnostic duplicate at our launch #4 (global #5 under ncu -s 5 -c 1):
    // full-grid k_chol on stale/zero g_Sigma. Data-independent control flow,
    // NaN-safe; g_Sigma and g_res are fully rewritten downstream, so the
    // final output is deterministic. Purpose: profile k_chol at true density.
    k_chol<<<NWIN, CT, SOLVE_SMEM>>>(Y);
    k_mean<<<NWIN, 256>>>();
    dim3 gs((TRI + 255) / 256, SIG_NCHUNK);
    k_sigma<<<gs, 256>>>();
    k_chol<<<NWIN, CT, SOLVE_SMEM>>>(Y);
    k_final<<<1, 256>>>((float*)d_out);
}

// round 15
// speedup vs baseline: 2.0257x; 2.0257x over previous
#include <cuda_runtime.h>
#include <math.h>

#define P        256
#define NT       480
#define NBLK     1000
#define NWIN     976
#define TRI      32896        // P*(P+1)/2
#define SIG_CHUNK  61
#define SIG_NCHUNK 16
#define LPS      260          // panel row stride (floats), %4==0
#define CT       128
#define SOLVE_SMEM ((16*LPS + 3*256 + 64) * 4)
#define FULLM 0xffffffffu

__device__ float g_wc[64];
__device__ float g_H[(size_t)NBLK * TRI];
__device__ float g_A[(size_t)NWIN * P * P];   // per-window column-major factor
__device__ float g_V[NBLK * P];
__device__ float g_mean[NWIN * P];
__device__ float g_res[2 * NWIN];

__device__ __forceinline__ int offj(int j) { return j * P - ((j * (j - 1)) >> 1); }

// ---------------- K0: weights & constants ---------------------------------
__global__ void k_setup(const float* __restrict__ a_in) {
    double a = (double)a_in[0];
    double s1 = 0.0, ap = 1.0;
    for (int u = 0; u < NT; u++) { s1 += ap; ap *= a; }
    double c = (double)NT / s1;
    double s2 = 0.0, a2 = a * a; ap = 1.0;
    for (int u = 0; u < NT; u++) { s2 += ap; ap *= a2; }
    s2 *= c * c;
    double denom = (double)NT - s2 / (double)NT;
    for (int k = 0; k < 24; k++) g_wc[k]      = (float)pow(a, 20.0 * (23 - k));
    for (int u = 0; u < 20; u++) g_wc[24 + u] = (float)pow(a, (double)(19 - u));
    g_wc[44] = (float)c;
    g_wc[45] = (float)(1.0 / denom);
    g_wc[46] = (float)pow(a, 20.0);
    g_wc[47] = (float)pow(a, 460.0);
    g_wc[48] = (float)(c / (double)NT);
}

// ---------------- K1: block Grams (packed lower) ---------------------------
__global__ void __launch_bounds__(256) k_gram(const float* __restrict__ Y) {
    const int lt = blockIdx.x % 10;
    const int b  = blockIdx.x / 10;
    int ti = 0;
    while (((ti + 1) * (ti + 2)) / 2 <= lt) ti++;
    const int tj = lt - (ti * (ti + 1)) / 2;

    __shared__ __align__(16) float As[20][64];
    __shared__ __align__(16) float Bs[20][64];
    __shared__ float Cs[64][65];
    const int tid = threadIdx.x;
    for (int idx = tid; idx < 20 * 64; idx += 256) {
        int u = idx >> 6, cc = idx & 63;
        size_t row = (size_t)(b * 20 + u) * P;
        As[u][cc] = g_wc[24 + u] * Y[row + ti * 64 + cc];
        Bs[u][cc] = Y[row + tj * 64 + cc];
    }
    __syncthreads();

    const int tx = tid & 15, ty = tid >> 4;
    float acc[4][4];
#pragma unroll
    for (int r = 0; r < 4; r++)
#pragma unroll
        for (int c = 0; c < 4; c++) acc[r][c] = 0.f;

#pragma unroll
    for (int u = 0; u < 20; u++) {
        float4 av = *(const float4*)&As[u][ty * 4];
        float4 bv = *(const float4*)&Bs[u][tx * 4];
        float ar[4] = {av.x, av.y, av.z, av.w};
        float br[4] = {bv.x, bv.y, bv.z, bv.w};
#pragma unroll
        for (int r = 0; r < 4; r++)
#pragma unroll
            for (int c = 0; c < 4; c++) acc[r][c] += ar[r] * br[c];
    }
#pragma unroll
    for (int r = 0; r < 4; r++)
#pragma unroll
        for (int c = 0; c < 4; c++) Cs[ty * 4 + r][tx * 4 + c] = acc[r][c];
    __syncthreads();

    float* Hb = g_H + (size_t)b * TRI;
    for (int idx = tid; idx < 64 * 64; idx += 256) {
        int cc = idx >> 6, rr = idx & 63;
        if (ti == tj && rr < cc) continue;
        int j = tj * 64 + cc, i = ti * 64 + rr;
        Hb[offj(j) + i - j] = Cs[rr][cc];
    }
}

// ---------------- K2: weighted block row-sums ------------------------------
__global__ void k_vsum(const float* __restrict__ Y) {
    const int b = blockIdx.x, i = threadIdx.x;
    float s = 0.f;
#pragma unroll
    for (int u = 0; u < 20; u++)
        s += g_wc[24 + u] * Y[(size_t)(b * 20 + u) * P + i];
    g_V[b * P + i] = s;
}

// ---------------- K3: per-window means --------------------------------------
__global__ void k_mean() {
    const int w = blockIdx.x, i = threadIdx.x;
    float s = 0.f;
#pragma unroll
    for (int k = 0; k < 24; k++)
        s += g_wc[k] * g_V[(w + k) * P + i];
    g_mean[w * P + i] = s * g_wc[48];
}

// ---------------- K4: Sigma -> g_A (column-major full layout) ---------------
__global__ void k_sigma() {
    int e = blockIdx.x * 256 + threadIdx.x;
    if (e >= TRI) return;
    int c = blockIdx.y;
    int j = (int)((513.0 - sqrt(513.0 * 513.0 - 8.0 * (double)e)) * 0.5);
    if (j < 0) j = 0; if (j > 255) j = 255;
    while (j < 255 && offj(j + 1) <= e) j++;
    while (j > 0 && offj(j) > e) j--;
    int i = e - offj(j) + j;

    const float a20 = g_wc[46], gg0 = g_wc[47], cw = g_wc[44], inv = g_wc[45];
    const int w0 = c * SIG_CHUNK;
    float T = 0.f;
    for (int k = 0; k < 24; k++) T += g_wc[k] * g_H[(size_t)(w0 + k) * TRI + e];
    const int ji = (j << 8) + i;
    for (int s = 0; s < SIG_CHUNK; s++) {
        int w = w0 + s;
        float m = g_mean[w * P + i] * g_mean[w * P + j];
        g_A[((size_t)w << 16) + ji] = (cw * T - 480.0f * m) * inv;
        if (s + 1 < SIG_CHUNK)
            T = a20 * (T - gg0 * g_H[(size_t)w * TRI + e]) + g_H[(size_t)(w + 24) * TRI + e];
    }
}

// ---------------- K5: out-of-core Cholesky, full col-major layout -----------
__global__ void __launch_bounds__(CT, 8) k_chol(const float* __restrict__ Y) {
    extern __shared__ float sm[];
    float* Lp  = sm;                      // 16 x LPS panel (abs row idx)
    float* yv  = Lp + 16 * LPS;           // 256
    float* zv  = yv + 256;                // 256
    float* rd  = zv + 256;                // 256: 1/L[j][j]
    float* red = rd + 256;                // 64 scratch
    const int w = blockIdx.x;
    const int tid = threadIdx.x;
    const int lane = tid & 31;
    const int wid  = tid >> 5;            // 0..3
    float* A = g_A + ((size_t)w << 16);   // column-major: A[(j<<8)+i]

    // ---- factorization: 16 panels of 16 ----
    for (int kb = 0; kb < 16; kb++) {
        const int j0  = 16 * kb;
        const int s0n = j0 + 16;
        const int hp  = P - s0n;

        // stage panel cols j0..j0+15 global -> smem (coalesced)
#pragma unroll 1
        for (int k = 0; k < 16; k++) {
            const float* colg = A + ((j0 + k) << 8);
            for (int i = j0 + k + tid; i < P; i += CT)
                Lp[k * LPS + i] = colg[i];
        }
        __syncthreads();

        // warp0: register Cholesky of 16x16 diag block (in panel)
        if (wid == 0) {
            const int r = lane;
            float a[16];
#pragma unroll
            for (int c = 0; c < 16; c++)
                a[c] = (r < 16 && r >= c) ? Lp[c * LPS + j0 + r] : 0.f;
#pragma unroll
            for (int jj = 0; jj < 16; jj++) {
                float d = __shfl_sync(FULLM, a[jj], jj);
                float rinv = rsqrtf(d);
                if (r == jj) rd[j0 + jj] = rinv;
                a[jj] *= rinv;
#pragma unroll
                for (int c = jj + 1; c < 16; c++) {
                    float Lcjj = __shfl_sync(FULLM, a[jj], c);
                    if (r >= c) a[c] -= a[jj] * Lcjj;
                }
            }
#pragma unroll
            for (int c = 0; c < 16; c++)
                if (r < 16 && r >= c) Lp[c * LPS + j0 + r] = a[c];
        }
        __syncthreads();

        // row-parallel TRSM (strided; hp up to 240, CT=128 -> <=2 passes)
        for (int i = s0n + tid; i < P; i += CT) {
            float y[16];
#pragma unroll
            for (int k = 0; k < 16; k++) y[k] = Lp[k * LPS + i];
#pragma unroll
            for (int k = 0; k < 16; k++) {
                y[k] *= rd[j0 + k];
                const float yk = y[k];
#pragma unroll
                for (int m = 1; m < 16; m++)
                    if (k + m < 16) y[k + m] -= Lp[k * LPS + j0 + k + m] * yk;
            }
#pragma unroll
            for (int k = 0; k < 16; k++) Lp[k * LPS + i] = y[k];
        }
        __syncthreads();

        // write back factored panel to global (coalesced)
#pragma unroll 1
        for (int k = 0; k < 16; k++) {
            float* colg = A + ((j0 + k) << 8);
            for (int i = j0 + k + tid; i < P; i += CT)
                colg[i] = Lp[k * LPS + i];
        }

        // trailing SYRK: 64-row x 8-col tiles, no integer division
        if (hp > 0) {
            const int mtr = (hp + 63) >> 6;
            const int ncj = hp >> 3;
            for (int bi = 0; bi < mtr; bi++) {
                const int i1 = s0n + (bi << 6) + lane;
                const int i2 = i1 + 32;
                const int cjmax = min(ncj, 8 * bi + 8);
                for (int cj = wid; cj < cjmax; cj += 4) {
                    const int jc0 = s0n + (cj << 3);
                    float acc1[8], acc2[8];
#pragma unroll
                    for (int c = 0; c < 8; c++) { acc1[c] = 0.f; acc2[c] = 0.f; }
#pragma unroll
                    for (int k = 0; k < 16; k++) {
                        const float* lk = Lp + k * LPS;
                        const float av1 = (i1 < P) ? lk[i1] : 0.f;  // coalesced LDS
                        const float av2 = (i2 < P) ? lk[i2] : 0.f;
                        float4 b0 = *(const float4*)&lk[jc0];       // broadcast
                        float4 b1 = *(const float4*)&lk[jc0 + 4];
                        float br[8] = {b0.x, b0.y, b0.z, b0.w, b1.x, b1.y, b1.z, b1.w};
#pragma unroll
                        for (int c = 0; c < 8; c++) {
                            acc1[c] = fmaf(av1, br[c], acc1[c]);
                            acc2[c] = fmaf(av2, br[c], acc2[c]);
                        }
                    }
                    if (i1 < P) {
                        float g[8];
#pragma unroll
                        for (int c = 0; c < 8; c++)
                            g[c] = (i1 >= jc0 + c) ? A[((jc0 + c) << 8) + i1] : 0.f;
#pragma unroll
                        for (int c = 0; c < 8; c++)
                            if (i1 >= jc0 + c) A[((jc0 + c) << 8) + i1] = g[c] - acc1[c];
                    }
                    if (i2 < P) {
                        float g[8];
#pragma unroll
                        for (int c = 0; c < 8; c++)
                            g[c] = (i2 >= jc0 + c) ? A[((jc0 + c) << 8) + i2] : 0.f;
#pragma unroll
                        for (int c = 0; c < 8; c++)
                            if (i2 >= jc0 + c) A[((jc0 + c) << 8) + i2] = g[c] - acc2[c];
                    }
                }
            }
        }
        __syncthreads();
    }

    // ---- forward: L y = 1 (L in global) ----
    for (int r = tid; r < P; r += CT) yv[r] = 1.0f;
    __syncthreads();
    for (int jb = 0; jb < 16; jb++) {
        const int j0 = jb * 16;
        if (wid == 0) {
            const int r = lane;
            float a[16];
#pragma unroll
            for (int c = 0; c < 16; c++)
                a[c] = (r < 16 && r >= c) ? A[((j0 + c) << 8) + j0 + r] : 0.f;
            float y   = (r < 16) ? yv[j0 + r] : 0.f;
            float rmy = (r < 16) ? rd[j0 + r] : 0.f;
#pragma unroll
            for (int jj = 0; jj < 16; jj++) {
                if (r == jj) y *= rmy;
                float yjj = __shfl_sync(FULLM, y, jj);
                if (r > jj && r < 16) y -= a[jj] * yjj;
            }
            if (r < 16) yv[j0 + r] = y;
        }
        __syncthreads();
        for (int r = j0 + 16 + tid; r < P; r += CT) {
            float s = 0.f;
#pragma unroll
            for (int jj = 0; jj < 16; jj++)
                s += A[((j0 + jj) << 8) + r] * yv[j0 + jj];
            yv[r] -= s;
        }
        __syncthreads();
    }

    // ---- backward: L^T z = y (gather form, coalesced column dots) ----
    for (int r = tid; r < P; r += CT) zv[r] = yv[r];
    __syncthreads();
    for (int jb = 15; jb >= 0; jb--) {
        const int j0 = jb * 16;
        const int base = j0 + 16, len = P - base;
        if (len > 0) {
#pragma unroll
            for (int h = 0; h < 4; h++) {
                const int j = j0 + wid + 4 * h;
                const float* colj = A + (j << 8);
                float s = 0.f;
                for (int r = base + lane; r < P; r += 32) s += colj[r] * zv[r];
#pragma unroll
                for (int o = 16; o > 0; o >>= 1) s += __shfl_down_sync(FULLM, s, o);
                if (lane == 0) red[wid + 4 * h] = s;
            }
        }
        __syncthreads();
        if (wid == 0) {
            const int c = lane;
            float a[16];
#pragma unroll
            for (int rr = 0; rr < 16; rr++)
                a[rr] = (c < 16 && rr >= c) ? A[((j0 + c) << 8) + j0 + rr] : 0.f;
            float corr = (c < 16 && len > 0) ? red[c] : 0.f;
            float z   = (c < 16) ? zv[j0 + c] - corr : 0.f;
            float rmz = (c < 16) ? rd[j0 + c] : 0.f;
#pragma unroll
            for (int jj = 15; jj >= 0; jj--) {
                if (c == jj) z *= rmz;
                float zjj = __shfl_sync(FULLM, z, jj);
                if (c < jj) z -= a[jj] * zjj;
            }
            if (c < 16) zv[j0 + c] = z;
        }
        __syncthreads();
    }

    // ---- normalize scale = 256 / sum(z) ----
    float s = zv[tid] + zv[tid + CT];
#pragma unroll
    for (int o = 16; o > 0; o >>= 1) s += __shfl_down_sync(FULLM, s, o);
    if (lane == 0) red[wid] = s;
    __syncthreads();
    if (tid == 0) {
        float tot = red[0] + red[1] + red[2] + red[3];
        red[40] = 256.0f / tot;
    }
    __syncthreads();
    const float scale = red[40];

    // ---- epilogue: 4 warps x 5 test days ----
#pragma unroll
    for (int kq = 0; kq < 5; kq++) {
        const int t = 4 * kq + wid;
        const float* yr = Y + (size_t)((w + 24) * 20 + t) * P;
        float part = 0.f;
#pragma unroll
        for (int q = 0; q < 8; q++)
            part += yr[lane + 32 * q] * zv[lane + 32 * q];
#pragma unroll
        for (int o = 16; o > 0; o >>= 1) part += __shfl_down_sync(FULLM, part, o);
        if (lane == 0) red[t] = part * scale;
    }
    __syncthreads();
    if (tid == 0) {
        float se = 0.f, sq = 0.f;
#pragma unroll
        for (int t = 0; t < 20; t++) { float rt = red[t]; se += rt; sq += rt * rt; }
        g_res[w] = se;
        g_res[NWIN + w] = (sq - se * se / 20.f) / 19.f;
    }
}

// ---------------- K6: final reduction ---------------------------------------
__global__ void k_final(float* out) {
    __shared__ float rb[64];
    const int tid = threadIdx.x;
    float se = 0.f, ss = 0.f;
    for (int w = tid; w < NWIN; w += 256) { se += g_res[w]; ss += g_res[NWIN + w]; }
#pragma unroll
    for (int o = 16; o > 0; o >>= 1) {
        se += __shfl_down_sync(FULLM, se, o);
        ss += __shfl_down_sync(FULLM, ss, o);
    }
    if ((tid & 31) == 0) { rb[tid >> 5] = se; rb[32 + (tid >> 5)] = ss; }
    __syncthreads();
    if (tid == 0) {
        float te = 0.f, ts = 0.f;
        for (int k = 0; k < 8; k++) { te += rb[k]; ts += rb[32 + k]; }
        float mu  = te / (float)NWIN / 20.f * 252.f;
        float vol = sqrtf(ts / (float)NWIN * 252.f);
        out[0] = vol;
        out[1] = mu;
        out[2] = mu / vol;
    }
}

extern "C" void kernel_launch(void* const* d_in, const int* in_sizes, int n_in,
                              void* d_out, int out_size) {
    const float* Y = (const float*)d_in[0];
    const float* a = (const float*)d_in[1];
    k_setup<<<1, 1>>>(a);
    k_gram<<<NBLK * 10, 256>>>(Y);
    k_vsum<<<NBLK, 256>>>(Y);
    k_mean<<<NWIN, 256>>>();
    dim3 gs((TRI + 255) / 256, SIG_NCHUNK);
    k_sigma<<<gs, 256>>>();
    k_chol<<<NWIN, CT, SOLVE_SMEM>>>(Y);
    k_final<<<1, 256>>>((float*)d_out);
}

// round 16
// speedup vs baseline: 2.1292x; 1.0511x over previous
#include <cuda_runtime.h>
#include <math.h>

#define P        256
#define NT       480
#define NBLK     1000
#define NWIN     976
#define TRI      32896        // P*(P+1)/2
#define SIG_CHUNK  61
#define SIG_NCHUNK 16
#define LPS      272          // panel row stride; rows [256,272) zero pad
#define CT       128
#define SOLVE_SMEM ((16*LPS + 3*256 + 64) * 4)
#define FULLM 0xffffffffu

__device__ float g_wc[64];
__device__ float g_H[(size_t)NBLK * TRI];
__device__ float g_A[(size_t)NWIN * P * P];   // per-window column-major factor
__device__ float g_V[NBLK * P];
__device__ float g_mean[NWIN * P];
__device__ float g_res[2 * NWIN];

__device__ __forceinline__ int offj(int j) { return j * P - ((j * (j - 1)) >> 1); }

// ---------------- K0: weights & constants ---------------------------------
__global__ void k_setup(const float* __restrict__ a_in) {
    double a = (double)a_in[0];
    double s1 = 0.0, ap = 1.0;
    for (int u = 0; u < NT; u++) { s1 += ap; ap *= a; }
    double c = (double)NT / s1;
    double s2 = 0.0, a2 = a * a; ap = 1.0;
    for (int u = 0; u < NT; u++) { s2 += ap; ap *= a2; }
    s2 *= c * c;
    double denom = (double)NT - s2 / (double)NT;
    for (int k = 0; k < 24; k++) g_wc[k]      = (float)pow(a, 20.0 * (23 - k));
    for (int u = 0; u < 20; u++) g_wc[24 + u] = (float)pow(a, (double)(19 - u));
    g_wc[44] = (float)c;
    g_wc[45] = (float)(1.0 / denom);
    g_wc[46] = (float)pow(a, 20.0);
    g_wc[47] = (float)pow(a, 460.0);
    g_wc[48] = (float)(c / (double)NT);
}

// ---------------- K1: block Grams (packed lower) ---------------------------
__global__ void __launch_bounds__(256) k_gram(const float* __restrict__ Y) {
    const int lt = blockIdx.x % 10;
    const int b  = blockIdx.x / 10;
    int ti = 0;
    while (((ti + 1) * (ti + 2)) / 2 <= lt) ti++;
    const int tj = lt - (ti * (ti + 1)) / 2;

    __shared__ __align__(16) float As[20][64];
    __shared__ __align__(16) float Bs[20][64];
    __shared__ float Cs[64][65];
    const int tid = threadIdx.x;
    for (int idx = tid; idx < 20 * 64; idx += 256) {
        int u = idx >> 6, cc = idx & 63;
        size_t row = (size_t)(b * 20 + u) * P;
        As[u][cc] = g_wc[24 + u] * Y[row + ti * 64 + cc];
        Bs[u][cc] = Y[row + tj * 64 + cc];
    }
    __syncthreads();

    const int tx = tid & 15, ty = tid >> 4;
    float acc[4][4];
#pragma unroll
    for (int r = 0; r < 4; r++)
#pragma unroll
        for (int c = 0; c < 4; c++) acc[r][c] = 0.f;

#pragma unroll
    for (int u = 0; u < 20; u++) {
        float4 av = *(const float4*)&As[u][ty * 4];
        float4 bv = *(const float4*)&Bs[u][tx * 4];
        float ar[4] = {av.x, av.y, av.z, av.w};
        float br[4] = {bv.x, bv.y, bv.z, bv.w};
#pragma unroll
        for (int r = 0; r < 4; r++)
#pragma unroll
            for (int c = 0; c < 4; c++) acc[r][c] += ar[r] * br[c];
    }
#pragma unroll
    for (int r = 0; r < 4; r++)
#pragma unroll
        for (int c = 0; c < 4; c++) Cs[ty * 4 + r][tx * 4 + c] = acc[r][c];
    __syncthreads();

    float* Hb = g_H + (size_t)b * TRI;
    for (int idx = tid; idx < 64 * 64; idx += 256) {
        int cc = idx >> 6, rr = idx & 63;
        if (ti == tj && rr < cc) continue;
        int j = tj * 64 + cc, i = ti * 64 + rr;
        Hb[offj(j) + i - j] = Cs[rr][cc];
    }
}

// ---------------- K2: weighted block row-sums ------------------------------
__global__ void k_vsum(const float* __restrict__ Y) {
    const int b = blockIdx.x, i = threadIdx.x;
    float s = 0.f;
#pragma unroll
    for (int u = 0; u < 20; u++)
        s += g_wc[24 + u] * Y[(size_t)(b * 20 + u) * P + i];
    g_V[b * P + i] = s;
}

// ---------------- K3: per-window means --------------------------------------
__global__ void k_mean() {
    const int w = blockIdx.x, i = threadIdx.x;
    float s = 0.f;
#pragma unroll
    for (int k = 0; k < 24; k++)
        s += g_wc[k] * g_V[(w + k) * P + i];
    g_mean[w * P + i] = s * g_wc[48];
}

// ---------------- K4: Sigma -> g_A (column-major full layout) ---------------
__global__ void k_sigma() {
    int e = blockIdx.x * 256 + threadIdx.x;
    if (e >= TRI) return;
    int c = blockIdx.y;
    int j = (int)((513.0 - sqrt(513.0 * 513.0 - 8.0 * (double)e)) * 0.5);
    if (j < 0) j = 0; if (j > 255) j = 255;
    while (j < 255 && offj(j + 1) <= e) j++;
    while (j > 0 && offj(j) > e) j--;
    int i = e - offj(j) + j;

    const float a20 = g_wc[46], gg0 = g_wc[47], cw = g_wc[44], inv = g_wc[45];
    const int w0 = c * SIG_CHUNK;
    float T = 0.f;
    for (int k = 0; k < 24; k++) T += g_wc[k] * g_H[(size_t)(w0 + k) * TRI + e];
    const int ji = (j << 8) + i;
    for (int s = 0; s < SIG_CHUNK; s++) {
        int w = w0 + s;
        float m = g_mean[w * P + i] * g_mean[w * P + j];
        g_A[((size_t)w << 16) + ji] = (cw * T - 480.0f * m) * inv;
        if (s + 1 < SIG_CHUNK)
            T = a20 * (T - gg0 * g_H[(size_t)w * TRI + e]) + g_H[(size_t)(w + 24) * TRI + e];
    }
}

// ---------------- K5: out-of-core Cholesky, col-major, padded panel ---------
__global__ void __launch_bounds__(CT, 8) k_chol(const float* __restrict__ Y) {
    extern __shared__ float sm[];
    float* Lp  = sm;                      // 16 x LPS panel (abs row idx, rows 256..271 = 0)
    float* yv  = Lp + 16 * LPS;           // 256
    float* zv  = yv + 256;                // 256
    float* rd  = zv + 256;                // 256: 1/L[j][j]
    float* red = rd + 256;                // 64 scratch
    const int w = blockIdx.x;
    const int tid = threadIdx.x;
    const int lane = tid & 31;
    const int wid  = tid >> 5;            // 0..3
    float* A = g_A + ((size_t)w << 16);   // column-major: A[(j<<8)+i]

    // zero pad rows once (they are never written again)
    for (int idx = tid; idx < 16 * 16; idx += CT)
        Lp[(idx >> 4) * LPS + 256 + (idx & 15)] = 0.f;

    // ---- factorization: 16 panels of 16 ----
    for (int kb = 0; kb < 16; kb++) {
        const int j0  = 16 * kb;
        const int s0n = j0 + 16;
        const int hp  = P - s0n;

        // stage panel cols j0..j0+15 global -> smem (coalesced)
#pragma unroll 1
        for (int k = 0; k < 16; k++) {
            const float* colg = A + ((j0 + k) << 8);
            for (int i = j0 + k + tid; i < P; i += CT)
                Lp[k * LPS + i] = colg[i];
        }
        __syncthreads();

        // warp0: register Cholesky of 16x16 diag block (in panel)
        if (wid == 0) {
            const int r = lane;
            float a[16];
#pragma unroll
            for (int c = 0; c < 16; c++)
                a[c] = (r < 16 && r >= c) ? Lp[c * LPS + j0 + r] : 0.f;
#pragma unroll
            for (int jj = 0; jj < 16; jj++) {
                float d = __shfl_sync(FULLM, a[jj], jj);
                float rinv = rsqrtf(d);
                if (r == jj) rd[j0 + jj] = rinv;
                a[jj] *= rinv;
#pragma unroll
                for (int c = jj + 1; c < 16; c++) {
                    float Lcjj = __shfl_sync(FULLM, a[jj], c);
                    if (r >= c) a[c] -= a[jj] * Lcjj;
                }
            }
#pragma unroll
            for (int c = 0; c < 16; c++)
                if (r < 16 && r >= c) Lp[c * LPS + j0 + r] = a[c];
        }
        __syncthreads();

        // row-parallel TRSM (strided; hp up to 240, CT=128 -> <=2 passes)
        for (int i = s0n + tid; i < P; i += CT) {
            float y[16];
#pragma unroll
            for (int k = 0; k < 16; k++) y[k] = Lp[k * LPS + i];
#pragma unroll
            for (int k = 0; k < 16; k++) {
                y[k] *= rd[j0 + k];
                const float yk = y[k];
#pragma unroll
                for (int m = 1; m < 16; m++)
                    if (k + m < 16) y[k + m] -= Lp[k * LPS + j0 + k + m] * yk;
            }
#pragma unroll
            for (int k = 0; k < 16; k++) Lp[k * LPS + i] = y[k];
        }
        __syncthreads();

        // write back factored panel to global (coalesced)
#pragma unroll 1
        for (int k = 0; k < 16; k++) {
            float* colg = A + ((j0 + k) << 8);
            for (int i = j0 + k + tid; i < P; i += CT)
                colg[i] = Lp[k * LPS + i];
        }

        // trailing SYRK: 32-row x 8-col tiles, guard-free k-loop, g prefetch
        if (hp > 0) {
            const int mtr = (hp + 31) >> 5;
            const int ncj = hp >> 3;
            for (int bi = 0; bi < mtr; bi++) {
                const int i = s0n + (bi << 5) + lane;  // may reach 271: pad rows are 0
                const int cjmax = min(ncj, 4 * bi + 4);
                for (int cj = wid; cj < cjmax; cj += 4) {
                    const int jc0 = s0n + (cj << 3);
                    // prefetch RMW targets (independent of k-loop)
                    float g[8];
                    if (i < P) {
#pragma unroll
                        for (int c = 0; c < 8; c++)
                            g[c] = (i >= jc0 + c) ? A[((jc0 + c) << 8) + i] : 0.f;
                    }
                    float acc[8];
#pragma unroll
                    for (int c = 0; c < 8; c++) acc[c] = 0.f;
#pragma unroll
                    for (int k = 0; k < 16; k++) {
                        const float* lk = Lp + k * LPS;
                        const float av = lk[i];              // coalesced, pad-safe
                        float4 b0 = *(const float4*)&lk[jc0];   // broadcast
                        float4 b1 = *(const float4*)&lk[jc0 + 4];
                        acc[0] = fmaf(av, b0.x, acc[0]);
                        acc[1] = fmaf(av, b0.y, acc[1]);
                        acc[2] = fmaf(av, b0.z, acc[2]);
                        acc[3] = fmaf(av, b0.w, acc[3]);
                        acc[4] = fmaf(av, b1.x, acc[4]);
                        acc[5] = fmaf(av, b1.y, acc[5]);
                        acc[6] = fmaf(av, b1.z, acc[6]);
                        acc[7] = fmaf(av, b1.w, acc[7]);
                    }
                    if (i < P) {
#pragma unroll
                        for (int c = 0; c < 8; c++)
                            if (i >= jc0 + c) A[((jc0 + c) << 8) + i] = g[c] - acc[c];
                    }
                }
            }
        }
        __syncthreads();
    }

    // ---- forward: L y = 1 (L in global) ----
    for (int r = tid; r < P; r += CT) yv[r] = 1.0f;
    __syncthreads();
    for (int jb = 0; jb < 16; jb++) {
        const int j0 = jb * 16;
        if (wid == 0) {
            const int r = lane;
            float a[16];
#pragma unroll
            for (int c = 0; c < 16; c++)
                a[c] = (r < 16 && r >= c) ? A[((j0 + c) << 8) + j0 + r] : 0.f;
            float y   = (r < 16) ? yv[j0 + r] : 0.f;
            float rmy = (r < 16) ? rd[j0 + r] : 0.f;
#pragma unroll
            for (int jj = 0; jj < 16; jj++) {
                if (r == jj) y *= rmy;
                float yjj = __shfl_sync(FULLM, y, jj);
                if (r > jj && r < 16) y -= a[jj] * yjj;
            }
            if (r < 16) yv[j0 + r] = y;
        }
        __syncthreads();
        for (int r = j0 + 16 + tid; r < P; r += CT) {
            float s = 0.f;
#pragma unroll
            for (int jj = 0; jj < 16; jj++)
                s += A[((j0 + jj) << 8) + r] * yv[j0 + jj];
            yv[r] -= s;
        }
        __syncthreads();
    }

    // ---- backward: L^T z = y (gather form, coalesced column dots) ----
    for (int r = tid; r < P; r += CT) zv[r] = yv[r];
    __syncthreads();
    for (int jb = 15; jb >= 0; jb--) {
        const int j0 = jb * 16;
        const int base = j0 + 16, len = P - base;
        if (len > 0) {
#pragma unroll
            for (int h = 0; h < 4; h++) {
                const int j = j0 + wid + 4 * h;
                const float* colj = A + (j << 8);
                float s = 0.f;
                for (int r = base + lane; r < P; r += 32) s += colj[r] * zv[r];
#pragma unroll
                for (int o = 16; o > 0; o >>= 1) s += __shfl_down_sync(FULLM, s, o);
                if (lane == 0) red[wid + 4 * h] = s;
            }
        }
        __syncthreads();
        if (wid == 0) {
            const int c = lane;
            float a[16];
#pragma unroll
            for (int rr = 0; rr < 16; rr++)
                a[rr] = (c < 16 && rr >= c) ? A[((j0 + c) << 8) + j0 + rr] : 0.f;
            float corr = (c < 16 && len > 0) ? red[c] : 0.f;
            float z   = (c < 16) ? zv[j0 + c] - corr : 0.f;
            float rmz = (c < 16) ? rd[j0 + c] : 0.f;
#pragma unroll
            for (int jj = 15; jj >= 0; jj--) {
                if (c == jj) z *= rmz;
                float zjj = __shfl_sync(FULLM, z, jj);
                if (c < jj) z -= a[jj] * zjj;
            }
            if (c < 16) zv[j0 + c] = z;
        }
        __syncthreads();
    }

    // ---- normalize scale = 256 / sum(z) ----
    float s = zv[tid] + zv[tid + CT];
#pragma unroll
    for (int o = 16; o > 0; o >>= 1) s += __shfl_down_sync(FULLM, s, o);
    if (lane == 0) red[wid] = s;
    __syncthreads();
    if (tid == 0) {
        float tot = red[0] + red[1] + red[2] + red[3];
        red[40] = 256.0f / tot;
    }
    __syncthreads();
    const float scale = red[40];

    // ---- epilogue: 4 warps x 5 test days ----
#pragma unroll
    for (int kq = 0; kq < 5; kq++) {
        const int t = 4 * kq + wid;
        const float* yr = Y + (size_t)((w + 24) * 20 + t) * P;
        float part = 0.f;
#pragma unroll
        for (int q = 0; q < 8; q++)
            part += yr[lane + 32 * q] * zv[lane + 32 * q];
#pragma unroll
        for (int o = 16; o > 0; o >>= 1) part += __shfl_down_sync(FULLM, part, o);
        if (lane == 0) red[t] = part * scale;
    }
    __syncthreads();
    if (tid == 0) {
        float se = 0.f, sq = 0.f;
#pragma unroll
        for (int t = 0; t < 20; t++) { float rt = red[t]; se += rt; sq += rt * rt; }
        g_res[w] = se;
        g_res[NWIN + w] = (sq - se * se / 20.f) / 19.f;
    }
}

// ---------------- K6: final reduction ---------------------------------------
__global__ void k_final(float* out) {
    __shared__ float rb[64];
    const int tid = threadIdx.x;
    float se = 0.f, ss = 0.f;
    for (int w = tid; w < NWIN; w += 256) { se += g_res[w]; ss += g_res[NWIN + w]; }
#pragma unroll
    for (int o = 16; o > 0; o >>= 1) {
        se += __shfl_down_sync(FULLM, se, o);
        ss += __shfl_down_sync(FULLM, ss, o);
    }
    if ((tid & 31) == 0) { rb[tid >> 5] = se; rb[32 + (tid >> 5)] = ss; }
    __syncthreads();
    if (tid == 0) {
        float te = 0.f, ts = 0.f;
        for (int k = 0; k < 8; k++) { te += rb[k]; ts += rb[32 + k]; }
        float mu  = te / (float)NWIN / 20.f * 252.f;
        float vol = sqrtf(ts / (float)NWIN * 252.f);
        out[0] = vol;
        out[1] = mu;
        out[2] = mu / vol;
    }
}

extern "C" void kernel_launch(void* const* d_in, const int* in_sizes, int n_in,
                              void* d_out, int out_size) {
    const float* Y = (const float*)d_in[0];
    const float* a = (const float*)d_in[1];
    k_setup<<<1, 1>>>(a);
    k_gram<<<NBLK * 10, 256>>>(Y);
    k_vsum<<<NBLK, 256>>>(Y);
    k_mean<<<NWIN, 256>>>();
    dim3 gs((TRI + 255) / 256, SIG_NCHUNK);
    k_sigma<<<gs, 256>>>();
    k_chol<<<NWIN, CT, SOLVE_SMEM>>>(Y);
    k_final<<<1, 256>>>((float*)d_out);
}